// round 2
// baseline (speedup 1.0000x reference)
#include <cuda_runtime.h>
#include <cstdint>
#include <cstddef>

#define NBATCH 4
#define NSEQ   2048
#define DIN    1024
#define NHEAD  16
#define DHEAD  64
#define NROWS  (NBATCH*NSEQ)   /* 8192 */
#define HDIM   (NHEAD*DHEAD)   /* 1024 */
#define SCALE  0.125f          /* 1/sqrt(64) */

// ---------------- scratch (device globals; no allocations allowed) ----------
__device__ float g_Q [NBATCH*NHEAD*NSEQ*DHEAD];   // (b,h,n,d)
__device__ float g_K [NBATCH*NHEAD*NSEQ*DHEAD];   // (b,h,n,d)
__device__ float g_Vt[NBATCH*NHEAD*DHEAD*NSEQ];   // (b,h,d,n)  (transposed V)
__device__ float g_C [NROWS*HDIM];                // context (b,n,h*64)
__device__ unsigned long long g_Mbits[(size_t)NROWS * (NSEQ/64)]; // packed mask
__device__ int   g_mask_esize;                    // 1, 2 or 4 bytes per mask elem

// ---------------- helpers ---------------------------------------------------
__device__ __forceinline__ unsigned f2tf(float f) {
    unsigned r; asm("cvt.rna.tf32.f32 %0, %1;" : "=r"(r) : "f"(f)); return r;
}
__device__ __forceinline__ void mma8(float* d, const unsigned* a, unsigned b0, unsigned b1) {
    asm volatile(
        "mma.sync.aligned.m16n8k8.row.col.f32.tf32.tf32.f32 "
        "{%0,%1,%2,%3}, {%4,%5,%6,%7}, {%8,%9}, {%0,%1,%2,%3};\n"
        : "+f"(d[0]), "+f"(d[1]), "+f"(d[2]), "+f"(d[3])
        : "r"(a[0]), "r"(a[1]), "r"(a[2]), "r"(a[3]), "r"(b0), "r"(b1));
}

// ---------------- mask dtype detection --------------------------------------
// bool mask may arrive as u8 {0,1}, i32 {0,1}, f32 {0,1.0f} or bf16 {0,0x3F80}.
// With ~50% random bits the 32-bit word patterns disambiguate with certainty.
__global__ void detect_kernel(const unsigned* __restrict__ w) {
    __shared__ int ok4s, ok2s;
    if (threadIdx.x == 0) { ok4s = 1; ok2s = 1; }
    __syncthreads();
    int ok4 = 1, ok2 = 1;
    for (int i = threadIdx.x; i < 4096; i += blockDim.x) {
        unsigned v = w[i];
        if (!(v == 0u || v == 1u || v == 0x3f800000u)) ok4 = 0;
        unsigned h0 = v & 0xffffu, h1 = v >> 16;
        if (!((h0 == 0u || h0 == 1u || h0 == 0x3f80u) &&
              (h1 == 0u || h1 == 1u || h1 == 0x3f80u))) ok2 = 0;
    }
    if (!ok4) atomicAnd(&ok4s, 0);
    if (!ok2) atomicAnd(&ok2s, 0);
    __syncthreads();
    if (threadIdx.x == 0) g_mask_esize = ok4s ? 4 : (ok2s ? 2 : 1);
}

// ---------------- mask bit-packing ------------------------------------------
// One thread builds one 64-bit word: bit j = (mask[row][w*64+j] != 0).
__global__ __launch_bounds__(256) void pack_kernel(const char* __restrict__ mp) {
    int idx = blockIdx.x * blockDim.x + threadIdx.x;        // 8192*32 words
    int row = idx >> 5, w = idx & 31;
    size_t ebase = (size_t)row * NSEQ + w * 64;
    int esz = g_mask_esize;
    unsigned long long bits = 0ull;
    if (esz == 4) {
        const unsigned* p = (const unsigned*)mp + ebase;
#pragma unroll
        for (int j = 0; j < 64; j++)
            bits |= (unsigned long long)(p[j] != 0u) << j;
    } else if (esz == 2) {
        const unsigned short* p = (const unsigned short*)mp + ebase;
#pragma unroll
        for (int j = 0; j < 64; j++)
            bits |= (unsigned long long)(p[j] != 0) << j;
    } else {
        const uchar4* p = (const uchar4*)(mp + ebase);
#pragma unroll
        for (int j = 0; j < 16; j++) {
            uchar4 v = p[j];
            bits |= (unsigned long long)(v.x != 0) << (4 * j + 0);
            bits |= (unsigned long long)(v.y != 0) << (4 * j + 1);
            bits |= (unsigned long long)(v.z != 0) << (4 * j + 2);
            bits |= (unsigned long long)(v.w != 0) << (4 * j + 3);
        }
    }
    g_Mbits[idx] = bits;
}

// ---------------- stage A: fused QKV projection ------------------------------
// grid (24, 64): x = 3 matrices x 8 col-tiles of 128; y = 64 row-tiles of 128.
// block 256 threads = 8 warps in a 4(M) x 2(N) grid; warp tile 32x64.
// launch_bounds(,2): cap 128 regs so 2 CTAs/SM overlap the single-buffered loads.
__global__ __launch_bounds__(256, 2) void qkv_kernel(
    const float* __restrict__ x,
    const float* __restrict__ Wq, const float* __restrict__ bq,
    const float* __restrict__ Wk, const float* __restrict__ bk,
    const float* __restrict__ Wv, const float* __restrict__ bv)
{
    __shared__ __align__(16) unsigned As[128][36];   // X tile, m-major, pad 36
    __shared__ __align__(16) unsigned Bs[32][136];   // W tile, k-major, pad 136

    const int tid  = threadIdx.x;
    const int wid  = tid >> 5, lane = tid & 31;
    const int g    = lane >> 2, q = lane & 3;
    const int wm   = wid >> 1, wn = wid & 1;

    const int wsel  = blockIdx.x >> 3;            // 0=Q,1=K,2=V
    const int ncol0 = (blockIdx.x & 7) * 128;
    const int mrow0 = blockIdx.y * 128;
    const float* W    = (wsel == 0) ? Wq : ((wsel == 1) ? Wk : Wv);
    const float* bias = (wsel == 0) ? bq : ((wsel == 1) ? bk : bv);

    float acc[2][8][4];
#pragma unroll
    for (int i = 0; i < 2; i++)
#pragma unroll
        for (int j = 0; j < 8; j++)
#pragma unroll
            for (int k = 0; k < 4; k++) acc[i][j][k] = 0.f;

    for (int kc = 0; kc < 32; kc++) {
        __syncthreads();
#pragma unroll
        for (int it = 0; it < 4; it++) {          // X tile 128x32
            int slot = it * 256 + tid;
            int r = slot >> 3, c4 = slot & 7;
            float4 v = *(const float4*)&x[(size_t)(mrow0 + r) * DIN + kc * 32 + c4 * 4];
            uint4 u; u.x = f2tf(v.x); u.y = f2tf(v.y); u.z = f2tf(v.z); u.w = f2tf(v.w);
            *(uint4*)&As[r][c4 * 4] = u;
        }
#pragma unroll
        for (int it = 0; it < 4; it++) {          // W tile 32x128
            int slot = it * 256 + tid;
            int r = slot >> 5, c4 = slot & 31;
            float4 v = *(const float4*)&W[(size_t)(kc * 32 + r) * HDIM + ncol0 + c4 * 4];
            uint4 u; u.x = f2tf(v.x); u.y = f2tf(v.y); u.z = f2tf(v.z); u.w = f2tf(v.w);
            *(uint4*)&Bs[r][c4 * 4] = u;
        }
        __syncthreads();
#pragma unroll
        for (int ks = 0; ks < 4; ks++) {
            int kk = ks * 8;
            unsigned a[2][4];
#pragma unroll
            for (int mt = 0; mt < 2; mt++) {
                int m = wm * 32 + mt * 16;
                a[mt][0] = As[m + g][kk + q];
                a[mt][1] = As[m + g + 8][kk + q];
                a[mt][2] = As[m + g][kk + q + 4];
                a[mt][3] = As[m + g + 8][kk + q + 4];
            }
#pragma unroll
            for (int nt = 0; nt < 8; nt++) {
                int n = wn * 64 + nt * 8 + g;
                unsigned b0 = Bs[kk + q][n];
                unsigned b1 = Bs[kk + q + 4][n];
                mma8(acc[0][nt], a[0], b0, b1);
                mma8(acc[1][nt], a[1], b0, b1);
            }
        }
    }

    // epilogue: +bias, round to tf32, scatter to (b,h,n,d) / transposed V
#pragma unroll
    for (int mt = 0; mt < 2; mt++) {
#pragma unroll
        for (int nt = 0; nt < 8; nt++) {
            int col = ncol0 + wn * 64 + nt * 8 + 2 * q;
            float b0 = bias[col], b1 = bias[col + 1];
            int h = col >> 6, d0 = col & 63;
#pragma unroll
            for (int rr = 0; rr < 2; rr++) {
                int r = mrow0 + wm * 32 + mt * 16 + g + rr * 8;
                int bb = r >> 11, n = r & 2047;
                float v0 = acc[mt][nt][rr * 2 + 0] + b0;
                float v1 = acc[mt][nt][rr * 2 + 1] + b1;
                if (wsel == 2) {
                    float* p = &g_Vt[(((size_t)bb * NHEAD + h) * DHEAD + d0) * NSEQ + n];
                    p[0]    = __uint_as_float(f2tf(v0));
                    p[NSEQ] = __uint_as_float(f2tf(v1));
                } else {
                    float* dst = (wsel == 0) ? g_Q : g_K;
                    float* p = &dst[(((size_t)bb * NHEAD + h) * NSEQ + n) * DHEAD + d0];
                    p[0] = __uint_as_float(f2tf(v0));
                    p[1] = __uint_as_float(f2tf(v1));
                }
            }
        }
    }
}

// ---------------- stage B: flash attention -----------------------------------
// grid (16, 64): x = query tiles of 128, y = b*H. block 256 = 8 warps x 16 rows.
// K/V staged in smem in B-fragment order; next chunk prefetched into registers
// while the current chunk computes (1 CTA/SM -> in-CTA latency hiding).
// Mask comes from the packed bit table: 2 broadcast LDG.64 per thread per chunk.
__global__ __launch_bounds__(256) void attn_kernel()
{
    __shared__ __align__(16) float Kf[8][8][64];     // [keytile][dstep][lane*2+i]
    __shared__ __align__(16) float Vf[8][8][64];     // [dtile][keystep][lane*2+i]

    const int tid = threadIdx.x;
    const int wid = tid >> 5, lane = tid & 31;
    const int g = lane >> 2, q = lane & 3;
    const int bh = blockIdx.y;
    const int b  = bh >> 4;
    const int q0 = blockIdx.x * 128;

    // Q rows for this lane (already tf32-rounded by stage A)
    unsigned qr[8][4];
    {
        const float* Qp  = &g_Q[((size_t)bh * NSEQ + q0 + wid * 16 + g) * DHEAD];
        const float* Qp8 = Qp + 8 * DHEAD;
#pragma unroll
        for (int s = 0; s < 8; s++) {
            qr[s][0] = __float_as_uint(Qp [8 * s + q]);
            qr[s][1] = __float_as_uint(Qp8[8 * s + q]);
            qr[s][2] = __float_as_uint(Qp [8 * s + q + 4]);
            qr[s][3] = __float_as_uint(Qp8[8 * s + q + 4]);
        }
    }

    float oacc[8][4];
#pragma unroll
    for (int u = 0; u < 8; u++)
#pragma unroll
        for (int k = 0; k < 4; k++) oacc[u][k] = 0.f;
    float l0 = 0.f, l1 = 0.f, m0 = -1e30f, m1 = -1e30f;

    const int rg = wid * 16 + g;
    const unsigned long long* Mrow0 = &g_Mbits[((size_t)b * NSEQ + q0 + rg) * (NSEQ / 64)];
    const unsigned long long* Mrow1 = Mrow0 + 8 * (NSEQ / 64);
    const int slo = (lane & 28) | (q >> 1);
    const int shi = slo + 2;
    const bool odd = (q & 1) != 0;

    // register prefetch buffers for the K/V chunk loads
    float4 kreg[4], vreg[4];
    const int ld_row = tid >> 4;          // 0..15 (key for K, d for V)
    const int ld_c   = tid & 15;          // float4 group 0..15
    auto load_chunk = [&](int k0) {
#pragma unroll
        for (int it = 0; it < 4; it++)
            kreg[it] = *(const float4*)&g_K[((size_t)bh * NSEQ + k0 + it * 16 + ld_row) * DHEAD + ld_c * 4];
#pragma unroll
        for (int it = 0; it < 4; it++)
            vreg[it] = *(const float4*)&g_Vt[((size_t)bh * DHEAD + it * 16 + ld_row) * NSEQ + k0 + ld_c * 4];
    };
    load_chunk(0);

    for (int ci = 0; ci < 32; ci++) {
        __syncthreads();                  // all warps done reading previous chunk
        // ---- store current chunk (fragment order), then prefetch next
        {
            int s = ld_c >> 1, i = ld_c & 1;
#pragma unroll
            for (int it = 0; it < 4; it++) {
                int key = it * 16 + ld_row;
                int t = key >> 3, gk = key & 7;
                float* dst = &Kf[t][s][i];
                dst[(gk * 4 + 0) * 2] = kreg[it].x;
                dst[(gk * 4 + 1) * 2] = kreg[it].y;
                dst[(gk * 4 + 2) * 2] = kreg[it].z;
                dst[(gk * 4 + 3) * 2] = kreg[it].w;
            }
#pragma unroll
            for (int it = 0; it < 4; it++) {
                int d = it * 16 + ld_row;
                int u = d >> 3, gv = d & 7;
                float* dst = &Vf[u][s][i];
                dst[(gv * 4 + 0) * 2] = vreg[it].x;
                dst[(gv * 4 + 1) * 2] = vreg[it].y;
                dst[(gv * 4 + 2) * 2] = vreg[it].z;
                dst[(gv * 4 + 3) * 2] = vreg[it].w;
            }
        }
        if (ci + 1 < 32) load_chunk((ci + 1) * 64);
        __syncthreads();

        // ---- mask words for this chunk (broadcast within lane quad; overlaps mma)
        unsigned long long w0 = Mrow0[ci] >> (2 * q);
        unsigned long long w1 = Mrow1[ci] >> (2 * q);

        // ---- S = Q K^T (16x64 per warp)
        float sacc[8][4];
#pragma unroll
        for (int t = 0; t < 8; t++)
#pragma unroll
            for (int k = 0; k < 4; k++) sacc[t][k] = 0.f;
#pragma unroll
        for (int s = 0; s < 8; s++) {
#pragma unroll
            for (int t = 0; t < 8; t++) {
                float2 bb = *(const float2*)&Kf[t][s][lane * 2];
                mma8(sacc[t], qr[s], __float_as_uint(bb.x), __float_as_uint(bb.y));
            }
        }

        // ---- scale + mask + online softmax (per lane-quad rows g, g+8)
        float mx0 = -1e30f, mx1 = -1e30f;
#pragma unroll
        for (int t = 0; t < 8; t++) {
            float s0 = sacc[t][0] * SCALE; if ((w0 >> (8 * t))     & 1) s0 = -1e9f;
            float s1 = sacc[t][1] * SCALE; if ((w0 >> (8 * t + 1)) & 1) s1 = -1e9f;
            float s2 = sacc[t][2] * SCALE; if ((w1 >> (8 * t))     & 1) s2 = -1e9f;
            float s3 = sacc[t][3] * SCALE; if ((w1 >> (8 * t + 1)) & 1) s3 = -1e9f;
            sacc[t][0] = s0; sacc[t][1] = s1; sacc[t][2] = s2; sacc[t][3] = s3;
            mx0 = fmaxf(mx0, fmaxf(s0, s1));
            mx1 = fmaxf(mx1, fmaxf(s2, s3));
        }
        mx0 = fmaxf(mx0, __shfl_xor_sync(~0u, mx0, 1));
        mx0 = fmaxf(mx0, __shfl_xor_sync(~0u, mx0, 2));
        mx1 = fmaxf(mx1, __shfl_xor_sync(~0u, mx1, 1));
        mx1 = fmaxf(mx1, __shfl_xor_sync(~0u, mx1, 2));

        float mn0 = fmaxf(m0, mx0), mn1 = fmaxf(m1, mx1);
        float al0 = __expf(m0 - mn0), al1 = __expf(m1 - mn1);
        m0 = mn0; m1 = mn1;
        l0 *= al0; l1 *= al1;
#pragma unroll
        for (int u = 0; u < 8; u++) {
            oacc[u][0] *= al0; oacc[u][1] *= al0;
            oacc[u][2] *= al1; oacc[u][3] *= al1;
        }
        // P = exp(S - m); store tf32 bits back into sacc storage (reg reuse)
#pragma unroll
        for (int t = 0; t < 8; t++) {
            float p0 = __expf(sacc[t][0] - mn0);
            float p1 = __expf(sacc[t][1] - mn0);
            float p2 = __expf(sacc[t][2] - mn1);
            float p3 = __expf(sacc[t][3] - mn1);
            l0 += p0 + p1; l1 += p2 + p3;
            sacc[t][0] = __uint_as_float(f2tf(p0));
            sacc[t][1] = __uint_as_float(f2tf(p1));
            sacc[t][2] = __uint_as_float(f2tf(p2));
            sacc[t][3] = __uint_as_float(f2tf(p3));
        }

        // ---- O += P V  (repack accumulator layout -> A-fragment via shfl)
#pragma unroll
        for (int s = 0; s < 8; s++) {
            unsigned e0 = __float_as_uint(sacc[s][0]);
            unsigned e1 = __float_as_uint(sacc[s][1]);
            unsigned e2 = __float_as_uint(sacc[s][2]);
            unsigned e3 = __float_as_uint(sacc[s][3]);
            unsigned t0 = __shfl_sync(~0u, e0, slo), t1 = __shfl_sync(~0u, e1, slo);
            unsigned t2 = __shfl_sync(~0u, e2, slo), t3 = __shfl_sync(~0u, e3, slo);
            unsigned h0 = __shfl_sync(~0u, e0, shi), h1 = __shfl_sync(~0u, e1, shi);
            unsigned h2 = __shfl_sync(~0u, e2, shi), h3 = __shfl_sync(~0u, e3, shi);
            unsigned a[4];
            a[0] = odd ? t1 : t0;
            a[1] = odd ? t3 : t2;
            a[2] = odd ? h1 : h0;
            a[3] = odd ? h3 : h2;
#pragma unroll
            for (int u = 0; u < 8; u++) {
                float2 bb = *(const float2*)&Vf[u][s][lane * 2];
                mma8(oacc[u], a, __float_as_uint(bb.x), __float_as_uint(bb.y));
            }
        }
    }

    // ---- finalize: 1/l, write context (tf32-rounded for stage C)
    l0 += __shfl_xor_sync(~0u, l0, 1); l0 += __shfl_xor_sync(~0u, l0, 2);
    l1 += __shfl_xor_sync(~0u, l1, 1); l1 += __shfl_xor_sync(~0u, l1, 2);
    float inv0 = 1.f / l0, inv1 = 1.f / l1;
    int h = bh & 15;
    int n0 = q0 + wid * 16 + g;
    float* Cp  = &g_C[((size_t)(b * NSEQ) + n0) * HDIM + h * DHEAD];
    float* Cp8 = Cp + 8 * HDIM;
#pragma unroll
    for (int u = 0; u < 8; u++) {
        int d0 = u * 8 + 2 * q;
        float2 v0, v1;
        v0.x = __uint_as_float(f2tf(oacc[u][0] * inv0));
        v0.y = __uint_as_float(f2tf(oacc[u][1] * inv0));
        v1.x = __uint_as_float(f2tf(oacc[u][2] * inv1));
        v1.y = __uint_as_float(f2tf(oacc[u][3] * inv1));
        *(float2*)&Cp [d0] = v0;
        *(float2*)&Cp8[d0] = v1;
    }
}

// ---------------- stage C: out = context @ Wo --------------------------------
// grid 128 blocks x 128 threads; block = 64 rows x 64 cols; warp = 16 rows.
__global__ __launch_bounds__(128) void proj_kernel(
    const float* __restrict__ Wo, float* __restrict__ out)
{
    __shared__ __align__(16) unsigned As[64][36];
    __shared__ __align__(16) unsigned Bs[32][72];
    const int tid = threadIdx.x;
    const int wid = tid >> 5, lane = tid & 31;
    const int g = lane >> 2, q = lane & 3;
    const int r0 = blockIdx.x * 64;

    float acc[8][4];
#pragma unroll
    for (int j = 0; j < 8; j++)
#pragma unroll
        for (int k = 0; k < 4; k++) acc[j][k] = 0.f;

    for (int kc = 0; kc < 32; kc++) {
        __syncthreads();
#pragma unroll
        for (int it = 0; it < 4; it++) {          // C tile 64x32 (already tf32)
            int slot = it * 128 + tid;
            int r = slot >> 3, c4 = slot & 7;
            uint4 v = *(const uint4*)&g_C[(size_t)(r0 + r) * HDIM + kc * 32 + c4 * 4];
            *(uint4*)&As[r][c4 * 4] = v;
        }
#pragma unroll
        for (int it = 0; it < 4; it++) {          // Wo tile 32x64
            int slot = it * 128 + tid;
            int r = slot >> 4, c4 = slot & 15;
            float4 v = *(const float4*)&Wo[(size_t)(kc * 32 + r) * DHEAD + c4 * 4];
            uint4 u; u.x = f2tf(v.x); u.y = f2tf(v.y); u.z = f2tf(v.z); u.w = f2tf(v.w);
            *(uint4*)&Bs[r][c4 * 4] = u;
        }
        __syncthreads();
#pragma unroll
        for (int ks = 0; ks < 4; ks++) {
            int kk = ks * 8;
            int m = wid * 16;
            unsigned a[4];
            a[0] = As[m + g][kk + q];
            a[1] = As[m + g + 8][kk + q];
            a[2] = As[m + g][kk + q + 4];
            a[3] = As[m + g + 8][kk + q + 4];
#pragma unroll
            for (int nt = 0; nt < 8; nt++) {
                unsigned b0 = Bs[kk + q][nt * 8 + g];
                unsigned b1 = Bs[kk + q + 4][nt * 8 + g];
                mma8(acc[nt], a, b0, b1);
            }
        }
    }
#pragma unroll
    for (int nt = 0; nt < 8; nt++) {
        int c0 = nt * 8 + 2 * q;
        int r = r0 + wid * 16 + g;
        *(float2*)&out[(size_t)r * DHEAD + c0]       = make_float2(acc[nt][0], acc[nt][1]);
        *(float2*)&out[(size_t)(r + 8) * DHEAD + c0] = make_float2(acc[nt][2], acc[nt][3]);
    }
}

// ---------------- launch -----------------------------------------------------
extern "C" void kernel_launch(void* const* d_in, const int* in_sizes, int n_in,
                              void* d_out, int out_size)
{
    const float* x    = (const float*)d_in[0];
    const void*  mask = d_in[1];
    const float* Wq   = (const float*)d_in[2];
    const float* bq   = (const float*)d_in[3];
    const float* Wk   = (const float*)d_in[4];
    const float* bk   = (const float*)d_in[5];
    const float* Wv   = (const float*)d_in[6];
    const float* bv   = (const float*)d_in[7];
    const float* Wo   = (const float*)d_in[8];
    float* out = (float*)d_out;

    detect_kernel<<<1, 256>>>((const unsigned*)mask);
    pack_kernel<<<(NROWS * (NSEQ / 64)) / 256, 256>>>((const char*)mask);
    qkv_kernel<<<dim3(24, 64), 256>>>(x, Wq, bq, Wk, bk, Wv, bv);
    attn_kernel<<<dim3(16, 64), 256>>>();
    proj_kernel<<<128, 128>>>(Wo, out);
}

// round 6
// speedup vs baseline: 1.3136x; 1.3136x over previous
#include <cuda_runtime.h>
#include <cstdint>
#include <cstddef>

#define NBATCH 4
#define NSEQ   2048
#define DIN    1024
#define NHEAD  16
#define DHEAD  64
#define NROWS  (NBATCH*NSEQ)   /* 8192 */
#define HDIM   (NHEAD*DHEAD)   /* 1024 */
#define SCALE  0.125f          /* 1/sqrt(64) */

// ---------------- scratch (device globals; no allocations allowed) ----------
// g_K / g_Vt hold K and V in FRAGMENT-CHUNK order:
//   flat = ((bh*32 + chunk)*4096) + (tile*8 + step)*64 + x
// K: tile t = key-tile, step s = d-step;  x encodes (key&7, d&7) so that the
//    float2 at x=2*lane is exactly lane's B-fragment (key=8t+g, d=8s+q|q+4).
// V: tile u = d-tile,  step s = key-step; x=2*lane -> (d=8u+g, key=8s+q|q+4).
__device__ float g_Q [NBATCH*NHEAD*NSEQ*DHEAD];   // (b,h,n,d) natural
__device__ float g_K [NBATCH*NHEAD*NSEQ*DHEAD];   // fragment-chunk order
__device__ float g_Vt[NBATCH*NHEAD*DHEAD*NSEQ];   // fragment-chunk order
__device__ float g_C [NROWS*HDIM];                // context (b,n,h*64)
__device__ unsigned long long g_Mbits[(size_t)NROWS * (NSEQ/64)]; // packed mask
__device__ int   g_mask_esize;                    // 1, 2 or 4 bytes per mask elem

// ---------------- helpers ---------------------------------------------------
__device__ __forceinline__ unsigned f2tf(float f) {
    unsigned r; asm("cvt.rna.tf32.f32 %0, %1;" : "=r"(r) : "f"(f)); return r;
}
__device__ __forceinline__ void mma8(float* d, const unsigned* a, unsigned b0, unsigned b1) {
    asm volatile(
        "mma.sync.aligned.m16n8k8.row.col.f32.tf32.tf32.f32 "
        "{%0,%1,%2,%3}, {%4,%5,%6,%7}, {%8,%9}, {%0,%1,%2,%3};\n"
        : "+f"(d[0]), "+f"(d[1]), "+f"(d[2]), "+f"(d[3])
        : "r"(a[0]), "r"(a[1]), "r"(a[2]), "r"(a[3]), "r"(b0), "r"(b1));
}
__device__ __forceinline__ void cpasync16(void* smem_dst, const void* gmem_src) {
    unsigned saddr = (unsigned)__cvta_generic_to_shared(smem_dst);
    asm volatile("cp.async.cg.shared.global [%0], [%1], 16;" :: "r"(saddr), "l"(gmem_src));
}

// ---------------- mask dtype detection --------------------------------------
__global__ void detect_kernel(const unsigned* __restrict__ w) {
    __shared__ int ok4s, ok2s;
    if (threadIdx.x == 0) { ok4s = 1; ok2s = 1; }
    __syncthreads();
    int ok4 = 1, ok2 = 1;
    for (int i = threadIdx.x; i < 4096; i += blockDim.x) {
        unsigned v = w[i];
        if (!(v == 0u || v == 1u || v == 0x3f800000u)) ok4 = 0;
        unsigned h0 = v & 0xffffu, h1 = v >> 16;
        if (!((h0 == 0u || h0 == 1u || h0 == 0x3f80u) &&
              (h1 == 0u || h1 == 1u || h1 == 0x3f80u))) ok2 = 0;
    }
    if (!ok4) atomicAnd(&ok4s, 0);
    if (!ok2) atomicAnd(&ok2s, 0);
    __syncthreads();
    if (threadIdx.x == 0) g_mask_esize = ok4s ? 4 : (ok2s ? 2 : 1);
}

// ---------------- mask bit-packing (ballot; coalesced) -----------------------
__global__ __launch_bounds__(256) void pack_kernel(const char* __restrict__ mp) {
    int wid = threadIdx.x >> 5, lane = threadIdx.x & 31;
    int row = blockIdx.x * 8 + wid;                 // grid 1024 -> 8192 rows
    size_t rbase = (size_t)row * NSEQ;
    int esz = g_mask_esize;
    for (int w = 0; w < 32; w++) {
        int e0 = w * 64 + lane, e1 = e0 + 32;
        bool b0, b1;
        if (esz == 4) {
            const unsigned* p = (const unsigned*)mp;
            b0 = p[rbase + e0] != 0u; b1 = p[rbase + e1] != 0u;
        } else if (esz == 2) {
            const unsigned short* p = (const unsigned short*)mp;
            b0 = p[rbase + e0] != 0; b1 = p[rbase + e1] != 0;
        } else {
            const unsigned char* p = (const unsigned char*)mp;
            b0 = p[rbase + e0] != 0; b1 = p[rbase + e1] != 0;
        }
        unsigned lo = __ballot_sync(~0u, b0);
        unsigned hi = __ballot_sync(~0u, b1);
        if (lane == 0)
            g_Mbits[(size_t)row * 32 + w] =
                (unsigned long long)lo | ((unsigned long long)hi << 32);
    }
}

// ---------------- stage A: fused QKV projection ------------------------------
__global__ __launch_bounds__(256, 2) void qkv_kernel(
    const float* __restrict__ x,
    const float* __restrict__ Wq, const float* __restrict__ bq,
    const float* __restrict__ Wk, const float* __restrict__ bk,
    const float* __restrict__ Wv, const float* __restrict__ bv)
{
    __shared__ __align__(16) unsigned As[128][36];
    __shared__ __align__(16) unsigned Bs[32][136];

    const int tid  = threadIdx.x;
    const int wid  = tid >> 5, lane = tid & 31;
    const int g    = lane >> 2, q = lane & 3;
    const int wm   = wid >> 1, wn = wid & 1;

    const int wsel  = blockIdx.x >> 3;            // 0=Q,1=K,2=V
    const int ncol0 = (blockIdx.x & 7) * 128;
    const int mrow0 = blockIdx.y * 128;
    const float* W    = (wsel == 0) ? Wq : ((wsel == 1) ? Wk : Wv);
    const float* bias = (wsel == 0) ? bq : ((wsel == 1) ? bk : bv);

    float acc[2][8][4];
#pragma unroll
    for (int i = 0; i < 2; i++)
#pragma unroll
        for (int j = 0; j < 8; j++)
#pragma unroll
            for (int k = 0; k < 4; k++) acc[i][j][k] = 0.f;

    for (int kc = 0; kc < 32; kc++) {
        __syncthreads();
#pragma unroll
        for (int it = 0; it < 4; it++) {
            int slot = it * 256 + tid;
            int r = slot >> 3, c4 = slot & 7;
            float4 v = *(const float4*)&x[(size_t)(mrow0 + r) * DIN + kc * 32 + c4 * 4];
            uint4 u; u.x = f2tf(v.x); u.y = f2tf(v.y); u.z = f2tf(v.z); u.w = f2tf(v.w);
            *(uint4*)&As[r][c4 * 4] = u;
        }
#pragma unroll
        for (int it = 0; it < 4; it++) {
            int slot = it * 256 + tid;
            int r = slot >> 5, c4 = slot & 31;
            float4 v = *(const float4*)&W[(size_t)(kc * 32 + r) * HDIM + ncol0 + c4 * 4];
            uint4 u; u.x = f2tf(v.x); u.y = f2tf(v.y); u.z = f2tf(v.z); u.w = f2tf(v.w);
            *(uint4*)&Bs[r][c4 * 4] = u;
        }
        __syncthreads();
#pragma unroll
        for (int ks = 0; ks < 4; ks++) {
            int kk = ks * 8;
            unsigned a[2][4];
#pragma unroll
            for (int mt = 0; mt < 2; mt++) {
                int m = wm * 32 + mt * 16;
                a[mt][0] = As[m + g][kk + q];
                a[mt][1] = As[m + g + 8][kk + q];
                a[mt][2] = As[m + g][kk + q + 4];
                a[mt][3] = As[m + g + 8][kk + q + 4];
            }
#pragma unroll
            for (int nt = 0; nt < 8; nt++) {
                int n = wn * 64 + nt * 8 + g;
                unsigned b0 = Bs[kk + q][n];
                unsigned b1 = Bs[kk + q + 4][n];
                mma8(acc[0][nt], a[0], b0, b1);
                mma8(acc[1][nt], a[1], b0, b1);
            }
        }
    }

#pragma unroll
    for (int mt = 0; mt < 2; mt++) {
#pragma unroll
        for (int nt = 0; nt < 8; nt++) {
            int col = ncol0 + wn * 64 + nt * 8 + 2 * q;
            float b0 = bias[col], b1 = bias[col + 1];
            int h = col >> 6, d0 = col & 63;
#pragma unroll
            for (int rr = 0; rr < 2; rr++) {
                int r = mrow0 + wm * 32 + mt * 16 + g + rr * 8;
                int bb = r >> 11, n = r & 2047;
                float v0 = acc[mt][nt][rr * 2 + 0] + b0;
                float v1 = acc[mt][nt][rr * 2 + 1] + b1;
                int bh = bb * 16 + h;
                if (wsel == 0) {
                    float* p = &g_Q[(((size_t)bh) * NSEQ + n) * DHEAD + d0];
                    p[0] = __uint_as_float(f2tf(v0));
                    p[1] = __uint_as_float(f2tf(v1));
                } else if (wsel == 1) {
                    // K fragment-chunk scatter: v0 at d0, v1 at d0+1 (flat +2)
                    int ci = n >> 6, keyin = n & 63;
                    int t = keyin >> 3, gk = keyin & 7;
                    size_t flat = (((size_t)bh * 32 + ci) * 4096)
                                + (size_t)(t * 8 + (d0 >> 3)) * 64
                                + (gk * 4 + (d0 & 3)) * 2 + ((d0 >> 2) & 1);
                    g_K[flat]     = __uint_as_float(f2tf(v0));
                    g_K[flat + 2] = __uint_as_float(f2tf(v1));
                } else {
                    // V fragment-chunk scatter: v0 at d0, v1 at d0+1 (flat +8)
                    int ci = n >> 6, keyin = n & 63;
                    int s = keyin >> 3;
                    size_t flat = (((size_t)bh * 32 + ci) * 4096)
                                + (size_t)((d0 >> 3) * 8 + s) * 64
                                + ((d0 & 7) * 4 + (keyin & 3)) * 2 + ((keyin >> 2) & 1);
                    g_Vt[flat]     = __uint_as_float(f2tf(v0));
                    g_Vt[flat + 8] = __uint_as_float(f2tf(v1));
                }
            }
        }
    }
}

// ---------------- stage B: flash attention -----------------------------------
// grid (8, 64); block 256 = 8 warps x 32 query rows (frag reuse x2).
// K/V arrive via cp.async into TRIPLE-buffered smem (fragment order already):
// zero mainloop smem stores, zero staging registers, ONE barrier per chunk.
__global__ __launch_bounds__(256) void attn_kernel()
{
    extern __shared__ __align__(16) float smem[];
    float* Kb = smem;             // [3][4096]
    float* Vb = smem + 3 * 4096;  // [3][4096]

    const int tid = threadIdx.x;
    const int wid = tid >> 5, lane = tid & 31;
    const int g = lane >> 2, q = lane & 3;
    const int bh = blockIdx.y;
    const int b  = bh >> 4;
    const int q0 = blockIdx.x * 256;

    const float* gKc = g_K  + (size_t)bh * (32 * 4096);
    const float* gVc = g_Vt + (size_t)bh * (32 * 4096);

    auto issue = [&](int ci, int buf) {
        const float* ks = gKc + (size_t)ci * 4096 + tid * 4;
        const float* vs = gVc + (size_t)ci * 4096 + tid * 4;
        float* kd = Kb + buf * 4096 + tid * 4;
        float* vd = Vb + buf * 4096 + tid * 4;
#pragma unroll
        for (int it = 0; it < 4; it++) {
            cpasync16(kd + it * 1024, ks + it * 1024);
            cpasync16(vd + it * 1024, vs + it * 1024);
        }
        asm volatile("cp.async.commit_group;");
    };

    issue(0, 0);
    issue(1, 1);

    // Q rows for this lane: warp tile rows wid*32 + mt*16 + {g, g+8}
    unsigned qr[2][8][4];
#pragma unroll
    for (int mt = 0; mt < 2; mt++) {
        const float* Qp  = &g_Q[((size_t)bh * NSEQ + q0 + wid * 32 + mt * 16 + g) * DHEAD];
        const float* Qp8 = Qp + 8 * DHEAD;
#pragma unroll
        for (int s = 0; s < 8; s++) {
            qr[mt][s][0] = __float_as_uint(Qp [8 * s + q]);
            qr[mt][s][1] = __float_as_uint(Qp8[8 * s + q]);
            qr[mt][s][2] = __float_as_uint(Qp [8 * s + q + 4]);
            qr[mt][s][3] = __float_as_uint(Qp8[8 * s + q + 4]);
        }
    }

    float oacc[2][8][4];
#pragma unroll
    for (int mt = 0; mt < 2; mt++)
#pragma unroll
        for (int u = 0; u < 8; u++)
#pragma unroll
            for (int k = 0; k < 4; k++) oacc[mt][u][k] = 0.f;
    float lsum[2][2], mrun[2][2];
#pragma unroll
    for (int mt = 0; mt < 2; mt++) { lsum[mt][0] = lsum[mt][1] = 0.f; mrun[mt][0] = mrun[mt][1] = -1e30f; }

    const int rg = wid * 32 + g;
    const unsigned long long* Mrow = &g_Mbits[((size_t)b * NSEQ + q0 + rg) * (NSEQ / 64)];
    const int slo = (lane & 28) | (q >> 1);
    const int shi = slo + 2;
    const bool odd = (q & 1) != 0;

    int buf = 0, bufnext = 2;     // buffer of chunk ci, and of chunk ci+2
    for (int ci = 0; ci < 32; ci++) {
        // chunk ci resident once <=1 newer group pending (ci+1 may still fly)
        if (ci < 31) asm volatile("cp.async.wait_group 1;");
        else         asm volatile("cp.async.wait_group 0;");
        __syncthreads();          // data visible AND buffer of ci-1 fully read
        if (ci + 2 < 32) issue(ci + 2, bufnext);   // overwrites buffer of ci-1
        const float* Kc = Kb + buf * 4096;
        const float* Vc = Vb + buf * 4096;
        buf = (buf + 1 == 3) ? 0 : buf + 1;
        bufnext = (bufnext + 1 == 3) ? 0 : bufnext + 1;

        // mask words: rows rg+{0,8,16,24}, pre-shifted for lane's 2q column base
        unsigned long long mw[2][2];
        mw[0][0] = Mrow[ci]                      >> (2 * q);
        mw[0][1] = Mrow[ci +  8 * (NSEQ / 64)]   >> (2 * q);
        mw[1][0] = Mrow[ci + 16 * (NSEQ / 64)]   >> (2 * q);
        mw[1][1] = Mrow[ci + 24 * (NSEQ / 64)]   >> (2 * q);

        // ---- S = Q K^T : one B-frag feeds both mt halves
        float sacc[2][8][4];
#pragma unroll
        for (int mt = 0; mt < 2; mt++)
#pragma unroll
            for (int t = 0; t < 8; t++)
#pragma unroll
                for (int k = 0; k < 4; k++) sacc[mt][t][k] = 0.f;
#pragma unroll
        for (int s = 0; s < 8; s++) {
#pragma unroll
            for (int t = 0; t < 8; t++) {
                float2 bb = *(const float2*)&Kc[(t * 8 + s) * 64 + lane * 2];
                unsigned b0 = __float_as_uint(bb.x), b1 = __float_as_uint(bb.y);
                mma8(sacc[0][t], qr[0][s], b0, b1);
                mma8(sacc[1][t], qr[1][s], b0, b1);
            }
        }

        // ---- scale + mask + online softmax per mt half
#pragma unroll
        for (int mt = 0; mt < 2; mt++) {
            float mx0 = -1e30f, mx1 = -1e30f;
#pragma unroll
            for (int t = 0; t < 8; t++) {
                float s0 = sacc[mt][t][0] * SCALE; if ((mw[mt][0] >> (8 * t))     & 1) s0 = -1e9f;
                float s1 = sacc[mt][t][1] * SCALE; if ((mw[mt][0] >> (8 * t + 1)) & 1) s1 = -1e9f;
                float s2 = sacc[mt][t][2] * SCALE; if ((mw[mt][1] >> (8 * t))     & 1) s2 = -1e9f;
                float s3 = sacc[mt][t][3] * SCALE; if ((mw[mt][1] >> (8 * t + 1)) & 1) s3 = -1e9f;
                sacc[mt][t][0] = s0; sacc[mt][t][1] = s1; sacc[mt][t][2] = s2; sacc[mt][t][3] = s3;
                mx0 = fmaxf(mx0, fmaxf(s0, s1));
                mx1 = fmaxf(mx1, fmaxf(s2, s3));
            }
            mx0 = fmaxf(mx0, __shfl_xor_sync(~0u, mx0, 1));
            mx0 = fmaxf(mx0, __shfl_xor_sync(~0u, mx0, 2));
            mx1 = fmaxf(mx1, __shfl_xor_sync(~0u, mx1, 1));
            mx1 = fmaxf(mx1, __shfl_xor_sync(~0u, mx1, 2));

            float mn0 = fmaxf(mrun[mt][0], mx0), mn1 = fmaxf(mrun[mt][1], mx1);
            float al0 = __expf(mrun[mt][0] - mn0), al1 = __expf(mrun[mt][1] - mn1);
            mrun[mt][0] = mn0; mrun[mt][1] = mn1;
            lsum[mt][0] *= al0; lsum[mt][1] *= al1;
#pragma unroll
            for (int u = 0; u < 8; u++) {
                oacc[mt][u][0] *= al0; oacc[mt][u][1] *= al0;
                oacc[mt][u][2] *= al1; oacc[mt][u][3] *= al1;
            }
            float l0 = 0.f, l1 = 0.f;
#pragma unroll
            for (int t = 0; t < 8; t++) {
                float p0 = __expf(sacc[mt][t][0] - mn0);
                float p1 = __expf(sacc[mt][t][1] - mn0);
                float p2 = __expf(sacc[mt][t][2] - mn1);
                float p3 = __expf(sacc[mt][t][3] - mn1);
                l0 += p0 + p1; l1 += p2 + p3;
                sacc[mt][t][0] = __uint_as_float(f2tf(p0));
                sacc[mt][t][1] = __uint_as_float(f2tf(p1));
                sacc[mt][t][2] = __uint_as_float(f2tf(p2));
                sacc[mt][t][3] = __uint_as_float(f2tf(p3));
            }
            lsum[mt][0] += l0; lsum[mt][1] += l1;
        }

        // ---- O += P V : one V-frag feeds both mt halves
#pragma unroll
        for (int s = 0; s < 8; s++) {
            unsigned a[2][4];
#pragma unroll
            for (int mt = 0; mt < 2; mt++) {
                unsigned e0 = __float_as_uint(sacc[mt][s][0]);
                unsigned e1 = __float_as_uint(sacc[mt][s][1]);
                unsigned e2 = __float_as_uint(sacc[mt][s][2]);
                unsigned e3 = __float_as_uint(sacc[mt][s][3]);
                unsigned t0 = __shfl_sync(~0u, e0, slo), t1 = __shfl_sync(~0u, e1, slo);
                unsigned t2 = __shfl_sync(~0u, e2, slo), t3 = __shfl_sync(~0u, e3, slo);
                unsigned h0 = __shfl_sync(~0u, e0, shi), h1 = __shfl_sync(~0u, e1, shi);
                unsigned h2 = __shfl_sync(~0u, e2, shi), h3 = __shfl_sync(~0u, e3, shi);
                a[mt][0] = odd ? t1 : t0;
                a[mt][1] = odd ? t3 : t2;
                a[mt][2] = odd ? h1 : h0;
                a[mt][3] = odd ? h3 : h2;
            }
#pragma unroll
            for (int u = 0; u < 8; u++) {
                float2 bb = *(const float2*)&Vc[(u * 8 + s) * 64 + lane * 2];
                unsigned b0 = __float_as_uint(bb.x), b1 = __float_as_uint(bb.y);
                mma8(oacc[0][u], a[0], b0, b1);
                mma8(oacc[1][u], a[1], b0, b1);
            }
        }
    }

    // ---- finalize: 1/l, write context (tf32-rounded for stage C)
    int h = bh & 15;
#pragma unroll
    for (int mt = 0; mt < 2; mt++) {
        float l0 = lsum[mt][0], l1 = lsum[mt][1];
        l0 += __shfl_xor_sync(~0u, l0, 1); l0 += __shfl_xor_sync(~0u, l0, 2);
        l1 += __shfl_xor_sync(~0u, l1, 1); l1 += __shfl_xor_sync(~0u, l1, 2);
        float inv0 = 1.f / l0, inv1 = 1.f / l1;
        int n0 = q0 + wid * 32 + mt * 16 + g;
        float* Cp  = &g_C[((size_t)(b * NSEQ) + n0) * HDIM + h * DHEAD];
        float* Cp8 = Cp + 8 * HDIM;
#pragma unroll
        for (int u = 0; u < 8; u++) {
            int d0 = u * 8 + 2 * q;
            float2 v0, v1;
            v0.x = __uint_as_float(f2tf(oacc[mt][u][0] * inv0));
            v0.y = __uint_as_float(f2tf(oacc[mt][u][1] * inv0));
            v1.x = __uint_as_float(f2tf(oacc[mt][u][2] * inv1));
            v1.y = __uint_as_float(f2tf(oacc[mt][u][3] * inv1));
            *(float2*)&Cp [d0] = v0;
            *(float2*)&Cp8[d0] = v1;
        }
    }
}

// ---------------- stage C: out = context @ Wo --------------------------------
__global__ __launch_bounds__(128) void proj_kernel(
    const float* __restrict__ Wo, float* __restrict__ out)
{
    __shared__ __align__(16) unsigned As[64][36];
    __shared__ __align__(16) unsigned Bs[32][72];
    const int tid = threadIdx.x;
    const int wid = tid >> 5, lane = tid & 31;
    const int g = lane >> 2, q = lane & 3;
    const int r0 = blockIdx.x * 64;

    float acc[8][4];
#pragma unroll
    for (int j = 0; j < 8; j++)
#pragma unroll
        for (int k = 0; k < 4; k++) acc[j][k] = 0.f;

    for (int kc = 0; kc < 32; kc++) {
        __syncthreads();
#pragma unroll
        for (int it = 0; it < 4; it++) {
            int slot = it * 128 + tid;
            int r = slot >> 3, c4 = slot & 7;
            uint4 v = *(const uint4*)&g_C[(size_t)(r0 + r) * HDIM + kc * 32 + c4 * 4];
            *(uint4*)&As[r][c4 * 4] = v;
        }
#pragma unroll
        for (int it = 0; it < 4; it++) {
            int slot = it * 128 + tid;
            int r = slot >> 4, c4 = slot & 15;
            float4 v = *(const float4*)&Wo[(size_t)(kc * 32 + r) * DHEAD + c4 * 4];
            uint4 u; u.x = f2tf(v.x); u.y = f2tf(v.y); u.z = f2tf(v.z); u.w = f2tf(v.w);
            *(uint4*)&Bs[r][c4 * 4] = u;
        }
        __syncthreads();
#pragma unroll
        for (int ks = 0; ks < 4; ks++) {
            int kk = ks * 8;
            int m = wid * 16;
            unsigned a[4];
            a[0] = As[m + g][kk + q];
            a[1] = As[m + g + 8][kk + q];
            a[2] = As[m + g][kk + q + 4];
            a[3] = As[m + g + 8][kk + q + 4];
#pragma unroll
            for (int nt = 0; nt < 8; nt++) {
                unsigned b0 = Bs[kk + q][nt * 8 + g];
                unsigned b1 = Bs[kk + q + 4][nt * 8 + g];
                mma8(acc[nt], a, b0, b1);
            }
        }
    }
#pragma unroll
    for (int nt = 0; nt < 8; nt++) {
        int c0 = nt * 8 + 2 * q;
        int r = r0 + wid * 16 + g;
        *(float2*)&out[(size_t)r * DHEAD + c0]       = make_float2(acc[nt][0], acc[nt][1]);
        *(float2*)&out[(size_t)(r + 8) * DHEAD + c0] = make_float2(acc[nt][2], acc[nt][3]);
    }
}

// ---------------- launch -----------------------------------------------------
extern "C" void kernel_launch(void* const* d_in, const int* in_sizes, int n_in,
                              void* d_out, int out_size)
{
    const float* x    = (const float*)d_in[0];
    const void*  mask = d_in[1];
    const float* Wq   = (const float*)d_in[2];
    const float* bq   = (const float*)d_in[3];
    const float* Wk   = (const float*)d_in[4];
    const float* bk   = (const float*)d_in[5];
    const float* Wv   = (const float*)d_in[6];
    const float* bv   = (const float*)d_in[7];
    const float* Wo   = (const float*)d_in[8];
    float* out = (float*)d_out;

    cudaFuncSetAttribute(attn_kernel,
                         cudaFuncAttributeMaxDynamicSharedMemorySize, 98304);

    detect_kernel<<<1, 256>>>((const unsigned*)mask);
    pack_kernel<<<1024, 256>>>((const char*)mask);
    qkv_kernel<<<dim3(24, 64), 256>>>(x, Wq, bq, Wk, bk, Wv, bv);
    attn_kernel<<<dim3(8, 64), 256, 98304>>>();
    proj_kernel<<<128, 128>>>(Wo, out);
}